// round 4
// baseline (speedup 1.0000x reference)
#include <cuda_runtime.h>
#include <math.h>

#define A_TOTAL 8732
#define N_GT    100
#define B_BATCH 64
#define EPSV    1e-6f
#define BA      (B_BATCH * A_TOTAL)

// Scratch (no allocations allowed -> __device__ globals)
__device__ unsigned long long g_gt_best[B_BATCH * N_GT];   // per (b,n): packed (iou_bits<<32)|(~a)
__device__ int   g_forced[BA];                              // per (b,a): forced gt index (last-wins) or -1
__device__ float g_best_iou[BA];                            // per (b,a): max iou over n
__device__ int   g_best_idx[BA];                            // per (b,a): first argmax over n

__global__ void k_init() {
    int i = blockIdx.x * blockDim.x + threadIdx.x;
    // key for iou=0, a=0 -> (0<<32)|0xFFFFFFFF ; all zero-iou anchors are <= this
    if (i < B_BATCH * N_GT) g_gt_best[i] = 0xFFFFFFFFull;
}

__global__ void __launch_bounds__(256) k_iou(
    const float4* __restrict__ gt_boxes,      // (B, N, 4) xyxy
    const float4* __restrict__ anchors_xyxy)  // (A, 4)
{
    __shared__ float4 s_gt[N_GT];
    __shared__ float  s_area[N_GT];
    __shared__ unsigned long long s_best[N_GT];

    const int b   = blockIdx.y;
    const int tid = threadIdx.x;

    if (tid < N_GT) {
        float4 g = gt_boxes[b * N_GT + tid];
        s_gt[tid] = g;
        s_area[tid] = __fmul_rn(__fsub_rn(g.z, g.x), __fsub_rn(g.w, g.y));
        s_best[tid] = 0xFFFFFFFFull;   // iou=0, a=0 sentinel
    }
    __syncthreads();

    const int a = blockIdx.x * blockDim.x + tid;
    if (a < A_TOTAL) {
        float4 an = anchors_xyxy[a];
        const float area_a = __fmul_rn(__fsub_rn(an.z, an.x), __fsub_rn(an.w, an.y));
        float best_iou = 0.0f;
        int   best_n   = 0;
        const unsigned int akey = 0xFFFFFFFFu - (unsigned int)a;

        #pragma unroll 4
        for (int n = 0; n < N_GT; n++) {
            float4 g = s_gt[n];
            float lx = fmaxf(an.x, g.x);
            float ly = fmaxf(an.y, g.y);
            float rx = fminf(an.z, g.z);
            float ry = fminf(an.w, g.w);
            float w = __fsub_rn(rx, lx);
            float h = __fsub_rn(ry, ly);
            if (w > 0.0f && h > 0.0f) {
                float inter = __fmul_rn(w, h);
                float uni   = __fsub_rn(__fadd_rn(area_a, s_area[n]), inter);
                float iou   = __fdiv_rn(inter, uni);   // bit-exact vs reference
                if (iou > best_iou) { best_iou = iou; best_n = n; }  // strict > : first max wins
                unsigned long long key =
                    ((unsigned long long)__float_as_uint(iou) << 32) | akey;
                if (key > s_best[n]) atomicMax(&s_best[n], key);
            }
        }
        const int o = b * A_TOTAL + a;
        g_best_iou[o] = best_iou;
        g_best_idx[o] = best_n;
        g_forced[o]   = -1;
    }
    __syncthreads();
    if (tid < N_GT) {
        unsigned long long v = s_best[tid];
        if (v > 0xFFFFFFFFull)  // only push if we beat the sentinel
            atomicMax(&g_gt_best[b * N_GT + tid], v);
    }
}

__global__ void k_assign() {
    int i = blockIdx.x * blockDim.x + threadIdx.x;   // i = b*N + n
    if (i < B_BATCH * N_GT) {
        int b = i / N_GT;
        int n = i - b * N_GT;
        unsigned int abest = 0xFFFFFFFFu - (unsigned int)(g_gt_best[i] & 0xFFFFFFFFull);
        // scatter with duplicate indices: last (largest) n wins -> atomicMax
        atomicMax(&g_forced[b * A_TOTAL + (int)abest], n);
    }
}

__global__ void __launch_bounds__(256) k_encode(
    const int*    __restrict__ gt_labels,       // (B, N)
    const float4* __restrict__ gt_boxes,        // (B, N, 4) xyxy
    const float4* __restrict__ anchors_cxcywh,  // (A, 4)
    float* __restrict__ out)
{
    const int a = blockIdx.x * blockDim.x + threadIdx.x;
    if (a >= A_TOTAL) return;
    const int b = blockIdx.y;
    const int i = b * A_TOTAL + a;

    int  f = g_forced[i];
    bool pos;
    int  idx;
    if (f >= 0) { pos = true; idx = f; }
    else        { idx = g_best_idx[i]; pos = g_best_iou[i] > 0.5f; }

    float4 g  = gt_boxes[b * N_GT + idx];          // xyxy
    float mcx = 0.5f * (g.x + g.z);
    float mcy = 0.5f * (g.y + g.w);
    float mw  = g.z - g.x;
    float mh  = g.w - g.y;

    float4 an = anchors_cxcywh[a];                  // cx, cy, w, h
    float ecx = (mcx - an.x) / an.z;
    float ecy = (mcy - an.y) / an.w;
    float ew  = logf((mw + EPSV) / (an.z + EPSV));
    float eh  = logf((mh + EPSV) / (an.w + EPSV));

    int lbl = pos ? gt_labels[b * N_GT + idx] : 0;

    // Output layout: [labels (BA)] [encoded (BA*4)] [pos_mask (BA)], all f32
    out[i] = (float)lbl;
    reinterpret_cast<float4*>(out + BA)[i] = make_float4(ecx, ecy, ew, eh);
    out[5 * BA + i] = pos ? 1.0f : 0.0f;
}

extern "C" void kernel_launch(void* const* d_in, const int* in_sizes, int n_in,
                              void* d_out, int out_size)
{
    const int*    gt_labels      = (const int*)   d_in[0];   // (64,100) int32
    const float4* gt_boxes       = (const float4*)d_in[1];   // (64,100,4) f32
    const float4* anchors_cxcywh = (const float4*)d_in[2];   // (8732,4) f32
    const float4* anchors_xyxy   = (const float4*)d_in[3];   // (8732,4) f32
    float*        out            = (float*)d_out;

    k_init<<<(B_BATCH * N_GT + 255) / 256, 256>>>();

    dim3 grid1((A_TOTAL + 255) / 256, B_BATCH);
    k_iou<<<grid1, 256>>>(gt_boxes, anchors_xyxy);

    k_assign<<<(B_BATCH * N_GT + 255) / 256, 256>>>();

    dim3 grid2((A_TOTAL + 255) / 256, B_BATCH);
    k_encode<<<grid2, 256>>>(gt_labels, gt_boxes, anchors_cxcywh, out);
}